// round 10
// baseline (speedup 1.0000x reference)
#include <cuda_runtime.h>
#include <cuda_fp16.h>
#include <mma.h>
#include <math_constants.h>

using namespace nvcuda;

#define NN 50000
#define IN_SIZE 128
#define HD 128        // NUM_HEADS * OUT_SIZE = 4*32
#define WPB 4         // warps (nodes) per block in edge kernel

#define AS 136        // fp16 smem row stride (mult of 8 for wmma, pad vs conflicts)
#define GEMM_SMEM ((128 * AS * 2) * 2)   // A + B tiles, fp16

// Scratch (device globals — no allocation allowed)
__device__ float g_h[(size_t)NN * HD];       // projected features, fp32 [N, H*D]

__device__ __forceinline__ uint2 f4_to_h4(float4 v)
{
    uint2 o;
    *reinterpret_cast<__half2*>(&o.x) = __floats2half2_rn(v.x, v.y);
    *reinterpret_cast<__half2*>(&o.y) = __floats2half2_rn(v.z, v.w);
    return o;
}
__device__ __forceinline__ float ex2(float x)
{
    float r;
    asm("ex2.approx.ftz.f32 %0, %1;" : "=f"(r) : "f"(x));
    return r;
}

// ---------------------------------------------------------------------------
// Kernel 1: h = feat @ W via HMMA tensor cores.
// 128x128 tile / block, 256 threads (8 warps). Full K=128 staged once in
// smem as fp16 (conversion fused into staging). Warp w: 32x64 output tile.
// Epilogue stores fp32 g_h.
// ---------------------------------------------------------------------------
__global__ void __launch_bounds__(256) proj_gemm_kernel(
    const float* __restrict__ feat, const float* __restrict__ W, int N)
{
    extern __shared__ __half smem[];
    __half* As = smem;                 // [128][AS]
    __half* Bs = smem + 128 * AS;      // [128][AS]

    const int t    = threadIdx.x;
    const int lane = t & 31;
    const int w    = t >> 5;
    const int r0   = blockIdx.x * 128;

    {
        const int row  = t >> 1;            // 0..127
        const int colb = (t & 1) * 64;      // 0 or 64
        const int ra   = min(r0 + row, N - 1);
#pragma unroll
        for (int i = 0; i < 16; i++) {
            const float4 fa = *(const float4*)&feat[(size_t)ra * IN_SIZE + colb + i * 4];
            *(uint2*)&As[row * AS + colb + i * 4] = f4_to_h4(fa);
            const float4 fb = *(const float4*)&W[row * HD + colb + i * 4];
            *(uint2*)&Bs[row * AS + colb + i * 4] = f4_to_h4(fb);
        }
    }
    __syncthreads();

    const int warp_row = (w & 3) * 32;
    const int warp_col = (w >> 2) * 64;

    wmma::fragment<wmma::accumulator, 16, 16, 16, float> acc[2][4];
#pragma unroll
    for (int i = 0; i < 2; i++)
#pragma unroll
        for (int j = 0; j < 4; j++)
            wmma::fill_fragment(acc[i][j], 0.f);

#pragma unroll
    for (int k0 = 0; k0 < 128; k0 += 16) {
        wmma::fragment<wmma::matrix_a, 16, 16, 16, __half, wmma::row_major> af[2];
        wmma::fragment<wmma::matrix_b, 16, 16, 16, __half, wmma::row_major> bf[4];
#pragma unroll
        for (int i = 0; i < 2; i++)
            wmma::load_matrix_sync(af[i], &As[(warp_row + i * 16) * AS + k0], AS);
#pragma unroll
        for (int j = 0; j < 4; j++)
            wmma::load_matrix_sync(bf[j], &Bs[k0 * AS + warp_col + j * 16], AS);
#pragma unroll
        for (int i = 0; i < 2; i++)
#pragma unroll
            for (int j = 0; j < 4; j++)
                wmma::mma_sync(acc[i][j], af[i], bf[j], acc[i][j]);
    }

    // epilogue: frags -> smem f32 (per-warp region) -> fp32 global
    __syncthreads();
    float* ep = (float*)smem + w * (32 * 64);
#pragma unroll
    for (int i = 0; i < 2; i++)
#pragma unroll
        for (int j = 0; j < 4; j++)
            wmma::store_matrix_sync(&ep[i * 16 * 64 + j * 16], acc[i][j], 64,
                                    wmma::mem_row_major);
    __syncwarp();

#pragma unroll
    for (int it = 0; it < 16; it++) {
        const int idx = it * 32 + lane;     // 32 rows x 16 float4
        const int row = idx >> 4;
        const int c4  = (idx & 15) * 4;
        const int rg  = r0 + warp_row + row;
        if (rg < N)
            *(float4*)&g_h[(size_t)rg * HD + warp_col + c4] =
                *(const float4*)&ep[row * 64 + c4];
    }
}

// ---------------------------------------------------------------------------
// Warp-cooperative lower_bound over sorted dst: first idx with dst[idx] >= v.
// 33-ary: 32 probes per round, range shrinks by 33x. ~4-5 rounds for E=1.6M.
// All lanes return the same value.
// ---------------------------------------------------------------------------
__device__ __forceinline__ int warp_lower_bound(
    const int* __restrict__ dst, int E, int v, int lane)
{
    int lo = 0, hi = E;
    while (hi - lo > 32) {
        const int step  = (hi - lo) / 33;            // >= 1
        const int probe = lo + (lane + 1) * step;    // strictly < hi
        const int cnt   = __popc(__ballot_sync(0xffffffffu,
                                               __ldg(&dst[probe]) < v));
        const int nlo = lo + cnt * step;
        const int nhi = (cnt < 32) ? lo + (cnt + 1) * step : hi;
        lo = nlo; hi = nhi;
    }
    const int idx = lo + lane;
    const unsigned b = __ballot_sync(0xffffffffu,
                                     (idx < hi) && (__ldg(&dst[idx]) < v));
    return lo + __popc(b);
}

// ---------------------------------------------------------------------------
// Kernel 2: fused edge phase — one warp per dst node. Finds its own segment
// via warp lower_bound (no rowptr kernel). fp32 gathers (LDG.128/lane),
// hv pre-scaled by log2e/sqrt(32), raw ex2, 4-edge unroll.
// ---------------------------------------------------------------------------
__global__ void __launch_bounds__(WPB * 32) edge_warp_kernel(
    const int* __restrict__ src, const int* __restrict__ dst,
    float* __restrict__ out, int N, int E)
{
    const int wid = threadIdx.x >> 5;
    const int l   = threadIdx.x & 31;
    const int v   = blockIdx.x * WPB + wid;
    if (v >= N) return;

    const int start = warp_lower_bound(dst, E, v, l);
    const int end   = warp_lower_bound(dst, E, v + 1, l);

    float4* outp = (float4*)&out[(size_t)v * HD + 4 * l];

    if (start >= end) {
        *outp = make_float4(0.f, 0.f, 0.f, 0.f);
        return;
    }

    const float C = 1.4426950408889634f * 0.17677669529663689f; // log2e/sqrt(32)
    float4 hv = *(const float4*)&g_h[(size_t)v * HD + 4 * l];
    hv.x *= C; hv.y *= C; hv.z *= C; hv.w *= C;

    float  sA = 0.f, sB = 0.f;
    float4 accA = make_float4(0.f, 0.f, 0.f, 0.f);
    float4 accB = make_float4(0.f, 0.f, 0.f, 0.f);

#define EDGE_ONE(srcidx)                                                    \
    do {                                                                    \
        const float4 a = *(const float4*)&g_h[(size_t)(srcidx) * HD + 4 * l];\
        float p = a.x * hv.x;                                               \
        p = fmaf(a.y, hv.y, p);                                             \
        p = fmaf(a.z, hv.z, p);                                             \
        p = fmaf(a.w, hv.w, p);                                             \
        p += __shfl_xor_sync(0xffffffffu, p, 1);                            \
        p += __shfl_xor_sync(0xffffffffu, p, 2);                            \
        p += __shfl_xor_sync(0xffffffffu, p, 4);                            \
        const float wt = ex2(p);                                            \
        sA += wt;                                                           \
        accA.x = fmaf(wt, a.x, accA.x);                                     \
        accA.y = fmaf(wt, a.y, accA.y);                                     \
        accA.z = fmaf(wt, a.z, accA.z);                                     \
        accA.w = fmaf(wt, a.w, accA.w);                                     \
    } while (0)

    int i = start;
    while (i < end && (i & 3)) { EDGE_ONE(__ldg(&src[i])); i++; }

    for (; i + 4 <= end; i += 4) {
        const int4 s4 = *(const int4*)&src[i];
        const float4 a = *(const float4*)&g_h[(size_t)s4.x * HD + 4 * l];
        const float4 b = *(const float4*)&g_h[(size_t)s4.y * HD + 4 * l];
        const float4 c = *(const float4*)&g_h[(size_t)s4.z * HD + 4 * l];
        const float4 d = *(const float4*)&g_h[(size_t)s4.w * HD + 4 * l];

        float pa = a.x * hv.x, pb = b.x * hv.x;
        float pc = c.x * hv.x, pd = d.x * hv.x;
        pa = fmaf(a.y, hv.y, pa);  pb = fmaf(b.y, hv.y, pb);
        pc = fmaf(c.y, hv.y, pc);  pd = fmaf(d.y, hv.y, pd);
        pa = fmaf(a.z, hv.z, pa);  pb = fmaf(b.z, hv.z, pb);
        pc = fmaf(c.z, hv.z, pc);  pd = fmaf(d.z, hv.z, pd);
        pa = fmaf(a.w, hv.w, pa);  pb = fmaf(b.w, hv.w, pb);
        pc = fmaf(c.w, hv.w, pc);  pd = fmaf(d.w, hv.w, pd);

        pa += __shfl_xor_sync(0xffffffffu, pa, 1);
        pb += __shfl_xor_sync(0xffffffffu, pb, 1);
        pc += __shfl_xor_sync(0xffffffffu, pc, 1);
        pd += __shfl_xor_sync(0xffffffffu, pd, 1);
        pa += __shfl_xor_sync(0xffffffffu, pa, 2);
        pb += __shfl_xor_sync(0xffffffffu, pb, 2);
        pc += __shfl_xor_sync(0xffffffffu, pc, 2);
        pd += __shfl_xor_sync(0xffffffffu, pd, 2);
        pa += __shfl_xor_sync(0xffffffffu, pa, 4);
        pb += __shfl_xor_sync(0xffffffffu, pb, 4);
        pc += __shfl_xor_sync(0xffffffffu, pc, 4);
        pd += __shfl_xor_sync(0xffffffffu, pd, 4);

        const float wa = ex2(pa);
        const float wb = ex2(pb);
        const float wc = ex2(pc);
        const float wd = ex2(pd);
        sA += wa + wc;
        sB += wb + wd;

        accA.x = fmaf(wa, a.x, accA.x);  accB.x = fmaf(wb, b.x, accB.x);
        accA.y = fmaf(wa, a.y, accA.y);  accB.y = fmaf(wb, b.y, accB.y);
        accA.z = fmaf(wa, a.z, accA.z);  accB.z = fmaf(wb, b.z, accB.z);
        accA.w = fmaf(wa, a.w, accA.w);  accB.w = fmaf(wb, b.w, accB.w);
        accA.x = fmaf(wc, c.x, accA.x);  accB.x = fmaf(wd, d.x, accB.x);
        accA.y = fmaf(wc, c.y, accA.y);  accB.y = fmaf(wd, d.y, accB.y);
        accA.z = fmaf(wc, c.z, accA.z);  accB.z = fmaf(wd, d.z, accB.z);
        accA.w = fmaf(wc, c.w, accA.w);  accB.w = fmaf(wd, d.w, accB.w);
    }
    for (; i < end; i++) EDGE_ONE(__ldg(&src[i]));
#undef EDGE_ONE

    const float inv = 1.f / (sA + sB);
    *outp = make_float4((accA.x + accB.x) * inv,
                        (accA.y + accB.y) * inv,
                        (accA.z + accB.z) * inv,
                        (accA.w + accB.w) * inv);
}

// ---------------------------------------------------------------------------
// Launch
// ---------------------------------------------------------------------------
extern "C" void kernel_launch(void* const* d_in, const int* in_sizes, int n_in,
                              void* d_out, int out_size)
{
    const float* feat = (const float*)d_in[0];
    const int*   src  = (const int*)d_in[1];
    const int*   dst  = (const int*)d_in[2];
    const float* W    = (const float*)d_in[3];
    float*       out  = (float*)d_out;

    const int N = in_sizes[0] / IN_SIZE;   // 50000
    const int E = in_sizes[1];             // 1600000

    static bool attr_done = false;
    if (!attr_done) {
        cudaFuncSetAttribute(proj_gemm_kernel,
                             cudaFuncAttributeMaxDynamicSharedMemorySize,
                             GEMM_SMEM);
        attr_done = true;
    }

    proj_gemm_kernel<<<(N + 127) / 128, 256, GEMM_SMEM>>>(feat, W, N);
    edge_warp_kernel<<<(N + WPB - 1) / WPB, WPB * 32>>>(src, dst, out, N, E);
}

// round 11
// speedup vs baseline: 1.1496x; 1.1496x over previous
#include <cuda_runtime.h>
#include <cuda_fp16.h>
#include <mma.h>
#include <math_constants.h>

using namespace nvcuda;

#define NN 50000
#define IN_SIZE 128
#define HD 128        // NUM_HEADS * OUT_SIZE = 4*32
#define WPB 8         // warps (nodes) per block in edge kernel
#define EPT 8         // edges per thread in rowptr part

#define AS 136        // fp16 smem row stride (mult of 8 for wmma, pad vs conflicts)
#define GEMM_SMEM ((128 * AS * 2) * 2)   // A + B tiles, fp16

// Scratch (device globals — no allocation allowed)
__device__ float g_h[(size_t)NN * HD];       // projected features, fp32 [N, H*D]
__device__ int   g_rowstart[NN + 1];         // CSR row pointer from sorted dst

__device__ __forceinline__ uint2 f4_to_h4(float4 v)
{
    uint2 o;
    *reinterpret_cast<__half2*>(&o.x) = __floats2half2_rn(v.x, v.y);
    *reinterpret_cast<__half2*>(&o.y) = __floats2half2_rn(v.z, v.w);
    return o;
}
__device__ __forceinline__ float ex2(float x)
{
    float r;
    asm("ex2.approx.ftz.f32 %0, %1;" : "=f"(r) : "f"(x));
    return r;
}

// ---------------------------------------------------------------------------
// Kernel 1 (fused pre-pass): blocks [0, RB) build the CSR row pointer by
// boundary scatter over sorted dst (independent work); blocks [RB, RB+G)
// compute h = feat @ W via HMMA tensor cores (128x128 tile, 256 thr, 8 warps,
// full K=128 staged once in smem as fp16). Rowptr blocks are 2 short waves
// that overlap with the GEMM instead of costing a serialized launch.
// ---------------------------------------------------------------------------
__global__ void __launch_bounds__(256) fused_pre_kernel(
    const float* __restrict__ feat, const float* __restrict__ W,
    const int* __restrict__ dst, int N, int E, int RB)
{
    // ---------------- rowptr part ----------------
    if (blockIdx.x < RB) {
        const int g  = blockIdx.x * blockDim.x + threadIdx.x;
        const int e0 = g * EPT;
        if (e0 >= E) return;

        int prev = (e0 == 0) ? -1 : __ldg(&dst[e0 - 1]);
        int last = prev;
#pragma unroll
        for (int j = 0; j < EPT; j++) {
            const int e = e0 + j;
            const int d = (e < E) ? __ldg(&dst[e]) : last;
            for (int v = last + 1; v <= d; v++) g_rowstart[v] = e;
            last = d;
        }
        if (e0 + EPT >= E) {                 // close the tail
            for (int v = last + 1; v <= N; v++) g_rowstart[v] = E;
        }
        return;
    }

    // ---------------- GEMM part ----------------
    extern __shared__ __half smem[];
    __half* As = smem;                 // [128][AS]
    __half* Bs = smem + 128 * AS;      // [128][AS]

    const int t    = threadIdx.x;
    const int lane = t & 31;
    const int w    = t >> 5;
    const int r0   = (blockIdx.x - RB) * 128;

    {
        const int row  = t >> 1;            // 0..127
        const int colb = (t & 1) * 64;      // 0 or 64
        const int ra   = min(r0 + row, N - 1);
#pragma unroll
        for (int i = 0; i < 16; i++) {
            const float4 fa = *(const float4*)&feat[(size_t)ra * IN_SIZE + colb + i * 4];
            *(uint2*)&As[row * AS + colb + i * 4] = f4_to_h4(fa);
            const float4 fb = *(const float4*)&W[row * HD + colb + i * 4];
            *(uint2*)&Bs[row * AS + colb + i * 4] = f4_to_h4(fb);
        }
    }
    __syncthreads();

    const int warp_row = (w & 3) * 32;
    const int warp_col = (w >> 2) * 64;

    wmma::fragment<wmma::accumulator, 16, 16, 16, float> acc[2][4];
#pragma unroll
    for (int i = 0; i < 2; i++)
#pragma unroll
        for (int j = 0; j < 4; j++)
            wmma::fill_fragment(acc[i][j], 0.f);

#pragma unroll
    for (int k0 = 0; k0 < 128; k0 += 16) {
        wmma::fragment<wmma::matrix_a, 16, 16, 16, __half, wmma::row_major> af[2];
        wmma::fragment<wmma::matrix_b, 16, 16, 16, __half, wmma::row_major> bf[4];
#pragma unroll
        for (int i = 0; i < 2; i++)
            wmma::load_matrix_sync(af[i], &As[(warp_row + i * 16) * AS + k0], AS);
#pragma unroll
        for (int j = 0; j < 4; j++)
            wmma::load_matrix_sync(bf[j], &Bs[k0 * AS + warp_col + j * 16], AS);
#pragma unroll
        for (int i = 0; i < 2; i++)
#pragma unroll
            for (int j = 0; j < 4; j++)
                wmma::mma_sync(acc[i][j], af[i], bf[j], acc[i][j]);
    }

    // epilogue: frags -> smem f32 (per-warp region) -> fp32 global
    __syncthreads();
    float* ep = (float*)smem + w * (32 * 64);
#pragma unroll
    for (int i = 0; i < 2; i++)
#pragma unroll
        for (int j = 0; j < 4; j++)
            wmma::store_matrix_sync(&ep[i * 16 * 64 + j * 16], acc[i][j], 64,
                                    wmma::mem_row_major);
    __syncwarp();

#pragma unroll
    for (int it = 0; it < 16; it++) {
        const int idx = it * 32 + lane;     // 32 rows x 16 float4
        const int row = idx >> 4;
        const int c4  = (idx & 15) * 4;
        const int rg  = r0 + warp_row + row;
        if (rg < N)
            *(float4*)&g_h[(size_t)rg * HD + warp_col + c4] =
                *(const float4*)&ep[row * 64 + c4];
    }
}

// ---------------------------------------------------------------------------
// Kernel 2: fused edge phase — one warp per dst node, no smem/barriers.
// fp32 gathers (1 LDG.128/lane = full row), hv pre-scaled by log2e/sqrt(32),
// raw ex2, 4-edge unroll (scalar src loads, no alignment pre-loop),
// split accumulators (a,c)->A / (b,d)->B halve the serial FMA chain.
// ---------------------------------------------------------------------------
__global__ void __launch_bounds__(WPB * 32) edge_warp_kernel(
    const int* __restrict__ src, float* __restrict__ out, int N)
{
    const int wid = threadIdx.x >> 5;
    const int l   = threadIdx.x & 31;
    const int v   = blockIdx.x * WPB + wid;
    if (v >= N) return;

    const int start = g_rowstart[v];
    const int end   = g_rowstart[v + 1];

    float4* outp = (float4*)&out[(size_t)v * HD + 4 * l];

    if (start >= end) {
        *outp = make_float4(0.f, 0.f, 0.f, 0.f);
        return;
    }

    const float C = 1.4426950408889634f * 0.17677669529663689f; // log2e/sqrt(32)
    float4 hv = *(const float4*)&g_h[(size_t)v * HD + 4 * l];
    hv.x *= C; hv.y *= C; hv.z *= C; hv.w *= C;

    float  sA = 0.f, sB = 0.f;
    float4 accA = make_float4(0.f, 0.f, 0.f, 0.f);
    float4 accB = make_float4(0.f, 0.f, 0.f, 0.f);

    int i = start;
    for (; i + 4 <= end; i += 4) {
        const int s0 = __ldg(&src[i]);
        const int s1 = __ldg(&src[i + 1]);
        const int s2 = __ldg(&src[i + 2]);
        const int s3 = __ldg(&src[i + 3]);
        const float4 a = *(const float4*)&g_h[(size_t)s0 * HD + 4 * l];
        const float4 b = *(const float4*)&g_h[(size_t)s1 * HD + 4 * l];
        const float4 c = *(const float4*)&g_h[(size_t)s2 * HD + 4 * l];
        const float4 d = *(const float4*)&g_h[(size_t)s3 * HD + 4 * l];

        float pa = a.x * hv.x, pb = b.x * hv.x;
        float pc = c.x * hv.x, pd = d.x * hv.x;
        pa = fmaf(a.y, hv.y, pa);  pb = fmaf(b.y, hv.y, pb);
        pc = fmaf(c.y, hv.y, pc);  pd = fmaf(d.y, hv.y, pd);
        pa = fmaf(a.z, hv.z, pa);  pb = fmaf(b.z, hv.z, pb);
        pc = fmaf(c.z, hv.z, pc);  pd = fmaf(d.z, hv.z, pd);
        pa = fmaf(a.w, hv.w, pa);  pb = fmaf(b.w, hv.w, pb);
        pc = fmaf(c.w, hv.w, pc);  pd = fmaf(d.w, hv.w, pd);

        pa += __shfl_xor_sync(0xffffffffu, pa, 1);
        pb += __shfl_xor_sync(0xffffffffu, pb, 1);
        pc += __shfl_xor_sync(0xffffffffu, pc, 1);
        pd += __shfl_xor_sync(0xffffffffu, pd, 1);
        pa += __shfl_xor_sync(0xffffffffu, pa, 2);
        pb += __shfl_xor_sync(0xffffffffu, pb, 2);
        pc += __shfl_xor_sync(0xffffffffu, pc, 2);
        pd += __shfl_xor_sync(0xffffffffu, pd, 2);
        pa += __shfl_xor_sync(0xffffffffu, pa, 4);
        pb += __shfl_xor_sync(0xffffffffu, pb, 4);
        pc += __shfl_xor_sync(0xffffffffu, pc, 4);
        pd += __shfl_xor_sync(0xffffffffu, pd, 4);

        const float wa = ex2(pa);
        const float wb = ex2(pb);
        const float wc = ex2(pc);
        const float wd = ex2(pd);
        sA += wa + wc;
        sB += wb + wd;

        accA.x = fmaf(wa, a.x, accA.x);  accB.x = fmaf(wb, b.x, accB.x);
        accA.y = fmaf(wa, a.y, accA.y);  accB.y = fmaf(wb, b.y, accB.y);
        accA.z = fmaf(wa, a.z, accA.z);  accB.z = fmaf(wb, b.z, accB.z);
        accA.w = fmaf(wa, a.w, accA.w);  accB.w = fmaf(wb, b.w, accB.w);
        accA.x = fmaf(wc, c.x, accA.x);  accB.x = fmaf(wd, d.x, accB.x);
        accA.y = fmaf(wc, c.y, accA.y);  accB.y = fmaf(wd, d.y, accB.y);
        accA.z = fmaf(wc, c.z, accA.z);  accB.z = fmaf(wd, d.z, accB.z);
        accA.w = fmaf(wc, c.w, accA.w);  accB.w = fmaf(wd, d.w, accB.w);
    }
    for (; i < end; i++) {
        const int s0 = __ldg(&src[i]);
        const float4 a = *(const float4*)&g_h[(size_t)s0 * HD + 4 * l];
        float p = a.x * hv.x;
        p = fmaf(a.y, hv.y, p);
        p = fmaf(a.z, hv.z, p);
        p = fmaf(a.w, hv.w, p);
        p += __shfl_xor_sync(0xffffffffu, p, 1);
        p += __shfl_xor_sync(0xffffffffu, p, 2);
        p += __shfl_xor_sync(0xffffffffu, p, 4);
        const float wt = ex2(p);
        sA += wt;
        accA.x = fmaf(wt, a.x, accA.x);
        accA.y = fmaf(wt, a.y, accA.y);
        accA.z = fmaf(wt, a.z, accA.z);
        accA.w = fmaf(wt, a.w, accA.w);
    }

    const float inv = 1.f / (sA + sB);
    *outp = make_float4((accA.x + accB.x) * inv,
                        (accA.y + accB.y) * inv,
                        (accA.z + accB.z) * inv,
                        (accA.w + accB.w) * inv);
}

// ---------------------------------------------------------------------------
// Launch
// ---------------------------------------------------------------------------
extern "C" void kernel_launch(void* const* d_in, const int* in_sizes, int n_in,
                              void* d_out, int out_size)
{
    const float* feat = (const float*)d_in[0];
    const int*   src  = (const int*)d_in[1];
    const int*   dst  = (const int*)d_in[2];
    const float* W    = (const float*)d_in[3];
    float*       out  = (float*)d_out;

    const int N = in_sizes[0] / IN_SIZE;   // 50000
    const int E = in_sizes[1];             // 1600000

    static bool attr_done = false;
    if (!attr_done) {
        cudaFuncSetAttribute(fused_pre_kernel,
                             cudaFuncAttributeMaxDynamicSharedMemorySize,
                             GEMM_SMEM);
        attr_done = true;
    }

    const int RB = (E / EPT + 255) / 256;          // rowptr blocks (first)
    const int GB = (N + 127) / 128;                // GEMM tile blocks
    fused_pre_kernel<<<RB + GB, 256, GEMM_SMEM>>>(feat, W, dst, N, E, RB);
    edge_warp_kernel<<<(N + WPB - 1) / WPB, WPB * 32>>>(src, out, N);
}

// round 12
// speedup vs baseline: 1.1947x; 1.0392x over previous
#include <cuda_runtime.h>
#include <cuda_fp16.h>
#include <mma.h>

using namespace nvcuda;

#define IN_SIZE 128
#define HD 128        // NUM_HEADS * OUT_SIZE = 4*32
#define EPT 32        // edges per thread in rowptr part (8 x int4 = 128B)
#define AS 136        // fp16 smem row stride for wmma
#define GEMM_SMEM ((128 * AS * 2) * 2)   // A + B tiles, fp16 (~68KB)
#define PERSIST_BLOCKS (148 * 5)

// Scratch (device globals — no allocation allowed)
__device__ float g_h[(size_t)50000 * HD];    // projected features fp32
__device__ int   g_rowstart[50001];          // CSR row pointer
__device__ int   g_counter;                  // work-stealing cursor

// ---------------------------------------------------------------------------
// helpers
// ---------------------------------------------------------------------------
__device__ __forceinline__ uint2 f4_to_h4(float4 v)
{
    uint2 o;
    *reinterpret_cast<__half2*>(&o.x) = __floats2half2_rn(v.x, v.y);
    *reinterpret_cast<__half2*>(&o.y) = __floats2half2_rn(v.z, v.w);
    return o;
}
__device__ __forceinline__ float ex2(float x)
{
    float r;
    asm("ex2.approx.ftz.f32 %0, %1;" : "=f"(r) : "f"(x));
    return r;
}
__device__ __forceinline__ void ffma2(unsigned long long& d,
                                      unsigned long long a,
                                      unsigned long long b)
{
    asm("fma.rn.f32x2 %0, %1, %2, %0;" : "+l"(d) : "l"(a), "l"(b));
}
__device__ __forceinline__ unsigned long long pack2(float x, float y)
{
    unsigned long long r;
    asm("mov.b64 %0, {%1, %2};" : "=l"(r) : "f"(x), "f"(y));
    return r;
}
__device__ __forceinline__ unsigned long long pack_dup(float x)
{
    unsigned long long r;
    asm("mov.b64 %0, {%1, %1};" : "=l"(r) : "f"(x));
    return r;
}
__device__ __forceinline__ float2 unpack2(unsigned long long v)
{
    float2 f;
    asm("mov.b64 {%0, %1}, %2;" : "=f"(f.x), "=f"(f.y) : "l"(v));
    return f;
}

// ---------------------------------------------------------------------------
// Kernel 1 (fused pre-pass): blocks [0, RB): rowptr boundary scatter over
// sorted dst (EPT=32, int4 loads). Blocks [RB, ...): HMMA GEMM h = feat @ W
// (128x128 tile, 256 thr, full K=128 in one fp16 smem stage).
// Also resets the work-stealing counter for kernel 2.
// ---------------------------------------------------------------------------
__global__ void __launch_bounds__(256) fused_pre_kernel(
    const float* __restrict__ feat, const float* __restrict__ W,
    const int* __restrict__ dst, int N, int E, int RB)
{
    if (blockIdx.x == 0 && threadIdx.x == 0) g_counter = 0;

    // ---------------- rowptr part ----------------
    if (blockIdx.x < RB) {
        const int g  = blockIdx.x * blockDim.x + threadIdx.x;
        const int e0 = g * EPT;
        if (e0 >= E) return;

        int last = (e0 == 0) ? -1 : __ldg(&dst[e0 - 1]);
#pragma unroll
        for (int j4 = 0; j4 < EPT / 4; j4++) {
            const int e = e0 + j4 * 4;
            int4 d4;
            if (e + 3 < E) {
                d4 = *(const int4*)&dst[e];
            } else {
                d4.x = (e     < E) ? __ldg(&dst[e])     : last;
                d4.y = (e + 1 < E) ? __ldg(&dst[e + 1]) : d4.x;
                d4.z = (e + 2 < E) ? __ldg(&dst[e + 2]) : d4.y;
                d4.w = (e + 3 < E) ? __ldg(&dst[e + 3]) : d4.z;
            }
            for (int v = last + 1;  v <= d4.x; v++) g_rowstart[v] = e;
            for (int v = d4.x + 1;  v <= d4.y; v++) g_rowstart[v] = e + 1;
            for (int v = d4.y + 1;  v <= d4.z; v++) g_rowstart[v] = e + 2;
            for (int v = d4.z + 1;  v <= d4.w; v++) g_rowstart[v] = e + 3;
            last = d4.w;
        }
        if (e0 + EPT >= E) {
            for (int v = last + 1; v <= N; v++) g_rowstart[v] = E;
        }
        return;
    }

    // ---------------- GEMM part ----------------
    extern __shared__ __half smem[];
    __half* As = smem;                 // [128][AS]
    __half* Bs = smem + 128 * AS;      // [128][AS]

    const int t    = threadIdx.x;
    const int lane = t & 31;
    const int w    = t >> 5;
    const int r0   = (blockIdx.x - RB) * 128;

    {
        const int row  = t >> 1;
        const int colb = (t & 1) * 64;
        const int ra   = min(r0 + row, N - 1);
#pragma unroll
        for (int i = 0; i < 16; i++) {
            const float4 fa = *(const float4*)&feat[(size_t)ra * IN_SIZE + colb + i * 4];
            *(uint2*)&As[row * AS + colb + i * 4] = f4_to_h4(fa);
            const float4 fb = *(const float4*)&W[row * HD + colb + i * 4];
            *(uint2*)&Bs[row * AS + colb + i * 4] = f4_to_h4(fb);
        }
    }
    __syncthreads();

    const int warp_row = (w & 3) * 32;
    const int warp_col = (w >> 2) * 64;

    wmma::fragment<wmma::accumulator, 16, 16, 16, float> acc[2][4];
#pragma unroll
    for (int i = 0; i < 2; i++)
#pragma unroll
        for (int j = 0; j < 4; j++)
            wmma::fill_fragment(acc[i][j], 0.f);

#pragma unroll
    for (int k0 = 0; k0 < 128; k0 += 16) {
        wmma::fragment<wmma::matrix_a, 16, 16, 16, __half, wmma::row_major> af[2];
        wmma::fragment<wmma::matrix_b, 16, 16, 16, __half, wmma::row_major> bf[4];
#pragma unroll
        for (int i = 0; i < 2; i++)
            wmma::load_matrix_sync(af[i], &As[(warp_row + i * 16) * AS + k0], AS);
#pragma unroll
        for (int j = 0; j < 4; j++)
            wmma::load_matrix_sync(bf[j], &Bs[k0 * AS + warp_col + j * 16], AS);
#pragma unroll
        for (int i = 0; i < 2; i++)
#pragma unroll
            for (int j = 0; j < 4; j++)
                wmma::mma_sync(acc[i][j], af[i], bf[j], acc[i][j]);
    }

    __syncthreads();
    float* ep = (float*)smem + w * (32 * 64);
#pragma unroll
    for (int i = 0; i < 2; i++)
#pragma unroll
        for (int j = 0; j < 4; j++)
            wmma::store_matrix_sync(&ep[i * 16 * 64 + j * 16], acc[i][j], 64,
                                    wmma::mem_row_major);
    __syncwarp();

#pragma unroll
    for (int it = 0; it < 16; it++) {
        const int idx = it * 32 + lane;
        const int row = idx >> 4;
        const int c4  = (idx & 15) * 4;
        const int rg  = r0 + warp_row + row;
        if (rg < N)
            *(float4*)&g_h[(size_t)rg * HD + warp_col + c4] =
                *(const float4*)&ep[row * 64 + c4];
    }
}

// ---------------------------------------------------------------------------
// Kernel 2: fused edge phase — persistent warps, work-stealing one node per
// atomicAdd. Packed f32x2 math: dot = 2 FFMA2 + FADD, acc = 2 FFMA2.
// hv pre-scaled by log2e/sqrt(32); raw ex2; 4-edge unroll for MLP.
// ---------------------------------------------------------------------------
__global__ void __launch_bounds__(256, 5) edge_warp_kernel(
    const int* __restrict__ src, float* __restrict__ out, int N)
{
    const int l = threadIdx.x & 31;
    const float C = 1.4426950408889634f * 0.17677669529663689f; // log2e/sqrt(32)

    for (;;) {
        int v;
        if (l == 0) v = atomicAdd(&g_counter, 1);
        v = __shfl_sync(0xffffffffu, v, 0);
        if (v >= N) return;

        const int start = g_rowstart[v];
        const int end   = g_rowstart[v + 1];
        float4* outp = (float4*)&out[(size_t)v * HD + 4 * l];

        if (start >= end) {
            *outp = make_float4(0.f, 0.f, 0.f, 0.f);
            continue;
        }

        float4 hv = *(const float4*)&g_h[(size_t)v * HD + 4 * l];
        const unsigned long long hp0 = pack2(hv.x * C, hv.y * C);
        const unsigned long long hp1 = pack2(hv.z * C, hv.w * C);

        float sA = 0.f, sB = 0.f;
        unsigned long long accA0 = 0ull, accA1 = 0ull;
        unsigned long long accB0 = 0ull, accB1 = 0ull;

        int i = start;
        for (; i + 4 <= end; i += 4) {
            const int s0 = __ldg(&src[i]);
            const int s1 = __ldg(&src[i + 1]);
            const int s2 = __ldg(&src[i + 2]);
            const int s3 = __ldg(&src[i + 3]);
            const ulonglong2 au = *(const ulonglong2*)&g_h[(size_t)s0 * HD + 4 * l];
            const ulonglong2 bu = *(const ulonglong2*)&g_h[(size_t)s1 * HD + 4 * l];
            const ulonglong2 cu = *(const ulonglong2*)&g_h[(size_t)s2 * HD + 4 * l];
            const ulonglong2 du = *(const ulonglong2*)&g_h[(size_t)s3 * HD + 4 * l];

            unsigned long long da = 0ull, db = 0ull, dc = 0ull, dd = 0ull;
            ffma2(da, au.x, hp0);  ffma2(db, bu.x, hp0);
            ffma2(dc, cu.x, hp0);  ffma2(dd, du.x, hp0);
            ffma2(da, au.y, hp1);  ffma2(db, bu.y, hp1);
            ffma2(dc, cu.y, hp1);  ffma2(dd, du.y, hp1);

            const float2 fa = unpack2(da);
            const float2 fb = unpack2(db);
            const float2 fc = unpack2(dc);
            const float2 fd = unpack2(dd);
            float pa = fa.x + fa.y;
            float pb = fb.x + fb.y;
            float pc = fc.x + fc.y;
            float pd = fd.x + fd.y;

            pa += __shfl_xor_sync(0xffffffffu, pa, 1);
            pb += __shfl_xor_sync(0xffffffffu, pb, 1);
            pc += __shfl_xor_sync(0xffffffffu, pc, 1);
            pd += __shfl_xor_sync(0xffffffffu, pd, 1);
            pa += __shfl_xor_sync(0xffffffffu, pa, 2);
            pb += __shfl_xor_sync(0xffffffffu, pb, 2);
            pc += __shfl_xor_sync(0xffffffffu, pc, 2);
            pd += __shfl_xor_sync(0xffffffffu, pd, 2);
            pa += __shfl_xor_sync(0xffffffffu, pa, 4);
            pb += __shfl_xor_sync(0xffffffffu, pb, 4);
            pc += __shfl_xor_sync(0xffffffffu, pc, 4);
            pd += __shfl_xor_sync(0xffffffffu, pd, 4);

            const float wa = ex2(pa);
            const float wb = ex2(pb);
            const float wc = ex2(pc);
            const float wd = ex2(pd);
            sA += wa + wc;
            sB += wb + wd;

            const unsigned long long wda = pack_dup(wa);
            const unsigned long long wdb = pack_dup(wb);
            const unsigned long long wdc = pack_dup(wc);
            const unsigned long long wdd = pack_dup(wd);
            ffma2(accA0, wda, au.x);  ffma2(accA1, wda, au.y);
            ffma2(accB0, wdb, bu.x);  ffma2(accB1, wdb, bu.y);
            ffma2(accA0, wdc, cu.x);  ffma2(accA1, wdc, cu.y);
            ffma2(accB0, wdd, du.x);  ffma2(accB1, wdd, du.y);
        }
        for (; i < end; i++) {
            const int s0 = __ldg(&src[i]);
            const ulonglong2 au = *(const ulonglong2*)&g_h[(size_t)s0 * HD + 4 * l];
            unsigned long long da = 0ull;
            ffma2(da, au.x, hp0);
            ffma2(da, au.y, hp1);
            const float2 fa = unpack2(da);
            float p = fa.x + fa.y;
            p += __shfl_xor_sync(0xffffffffu, p, 1);
            p += __shfl_xor_sync(0xffffffffu, p, 2);
            p += __shfl_xor_sync(0xffffffffu, p, 4);
            const float wt = ex2(p);
            sA += wt;
            const unsigned long long wdt = pack_dup(wt);
            ffma2(accA0, wdt, au.x);
            ffma2(accA1, wdt, au.y);
        }

        const float inv = 1.f / (sA + sB);
        const float2 a0 = unpack2(accA0);
        const float2 a1 = unpack2(accA1);
        const float2 b0 = unpack2(accB0);
        const float2 b1 = unpack2(accB1);
        *outp = make_float4((a0.x + b0.x) * inv,
                            (a0.y + b0.y) * inv,
                            (a1.x + b1.x) * inv,
                            (a1.y + b1.y) * inv);
    }
}

// ---------------------------------------------------------------------------
// Launch
// ---------------------------------------------------------------------------
extern "C" void kernel_launch(void* const* d_in, const int* in_sizes, int n_in,
                              void* d_out, int out_size)
{
    const float* feat = (const float*)d_in[0];
    const int*   src  = (const int*)d_in[1];
    const int*   dst  = (const int*)d_in[2];
    const float* W    = (const float*)d_in[3];
    float*       out  = (float*)d_out;

    const int N = in_sizes[0] / IN_SIZE;   // 50000
    const int E = in_sizes[1];             // 1600000

    static bool attr_done = false;
    if (!attr_done) {
        cudaFuncSetAttribute(fused_pre_kernel,
                             cudaFuncAttributeMaxDynamicSharedMemorySize,
                             GEMM_SMEM);
        attr_done = true;
    }

    const int RB = (E / EPT + 255) / 256;          // rowptr blocks (first)
    const int GB = (N + 127) / 128;                // GEMM tile blocks
    fused_pre_kernel<<<RB + GB, 256, GEMM_SMEM>>>(feat, W, dst, N, E, RB);

    int nb = (N + 7) / 8;
    if (nb > PERSIST_BLOCKS) nb = PERSIST_BLOCKS;
    edge_warp_kernel<<<nb, 256>>>(src, out, N);
}